// round 15
// baseline (speedup 1.0000x reference)
#include <cuda_runtime.h>
#include <cstdint>

#define BB 4
#define HH 16
#define DD 4
#define HID 256
#define NN 1024
#define LOG2E 1.4426950408889634f
#define QPRE (0.5f * LOG2E)   /* SCALE * log2(e), folded into q at projection time */

// ---------------- device scratch (no allocation allowed) ----------------
// split-K partial slots: [kh][...]; consumers sum the two slots.
__device__ float g_qh[2][BB*HH*NN*DD];   // [b][h][n][d], pre-scaled by QPRE
__device__ float g_kd[2][BB*HH*DD*NN];   // [b][h][d][n]
__device__ float g_vd[2][BB*HH*DD*NN];   // [b][h][d][n]
__device__ float g_x2[BB*HH*DD*NN];      // [b][h*4+d][n]  (post-transpose layout)

__device__ __forceinline__ float ex2f(float x){
    float y; asm("ex2.approx.ftz.f32 %0, %1;" : "=f"(y) : "f"(x)); return y;
}
__device__ __forceinline__ float wred(float v){
    v += __shfl_xor_sync(0xffffffffu, v, 16);
    v += __shfl_xor_sync(0xffffffffu, v, 8);
    v += __shfl_xor_sync(0xffffffffu, v, 4);
    v += __shfl_xor_sync(0xffffffffu, v, 2);
    v += __shfl_xor_sync(0xffffffffu, v, 1);
    return v;
}

// ---- packed f32x2 helpers (PTX ISA 8.6+, sm_100+) ----
__device__ __forceinline__ uint64_t fma2(uint64_t a, uint64_t b, uint64_t c){
    uint64_t d; asm("fma.rn.f32x2 %0, %1, %2, %3;" : "=l"(d) : "l"(a), "l"(b), "l"(c)); return d;
}
__device__ __forceinline__ uint64_t mul2(uint64_t a, uint64_t b){
    uint64_t d; asm("mul.rn.f32x2 %0, %1, %2;" : "=l"(d) : "l"(a), "l"(b)); return d;
}
__device__ __forceinline__ uint64_t add2(uint64_t a, uint64_t b){
    uint64_t d; asm("add.rn.f32x2 %0, %1, %2;" : "=l"(d) : "l"(a), "l"(b)); return d;
}
__device__ __forceinline__ uint64_t pack2(float lo, float hi){
    uint64_t d; asm("mov.b64 %0, {%1, %2};" : "=l"(d) : "f"(lo), "f"(hi)); return d;
}
__device__ __forceinline__ void unpack2(uint64_t p, float& lo, float& hi){
    asm("mov.b64 {%0, %1}, %2;" : "=f"(lo), "=f"(hi) : "l"(p));
}

#define WT_PITCH 68   /* floats; 272B rows, 16B-aligned */
#define KCHUNK 64

// ---------------- kernel 1: smem-tiled f32x2 GEMM, split-K to slots -------------
// grid (64, BB, 3): x = (n-tile [0,32) | k-half<<5), y = batch, z = projection.
// block 128: mg = t&15 -> 4 consecutive M (2 packed pairs), ng = t>>4 -> 4 N.
// Each CTA covers K range [kh*128, kh*128+128); partials go to slot kh (plain stores).
__global__ void __launch_bounds__(128) proj_kernel(
    const float* __restrict__ q,
    const float* __restrict__ k,
    const float* __restrict__ v,
    const float* __restrict__ Wq,
    const float* __restrict__ Wk,
    const float* __restrict__ Wv)
{
    __shared__ __align__(16) float xs[KCHUNK * 32];
    __shared__ __align__(16) float Wt[KCHUNK * WT_PITCH];

    const int z   = blockIdx.z;
    const int b   = blockIdx.y;
    const int nt  = blockIdx.x & 31;
    const int kh  = blockIdx.x >> 5;           // k-half: 0 or 1
    const int n0g = nt * 32;

    const float* x = (z == 0) ? q : (z == 1) ? k : v;
    const float* W = (z == 0) ? Wq : (z == 1) ? Wk : Wv;

    const int t   = threadIdx.x;
    const int mg  = t & 15;
    const int ng  = t >> 4;            // [0,8)
    const int m0  = mg * 4;
    const int nt0 = ng * 4;

    uint64_t acc[2][4];
    #pragma unroll
    for (int p = 0; p < 2; p++)
        #pragma unroll
        for (int j = 0; j < 4; j++) acc[p][j] = 0ull;

    const float* xb = x + (size_t)b * HID * NN + n0g;

    const int kbeg = kh * 128;
    for (int k0 = kbeg; k0 < kbeg + 128; k0 += KCHUNK) {
        __syncthreads();
        // stage x chunk [64k x 32n], coalesced
        {
            const int kk = t >> 3;          // [0,16)
            const int nn = (t & 7) * 4;
            #pragma unroll
            for (int p = 0; p < 4; p++) {
                const int kr = kk + p * 16;
                *(float4*)&xs[kr * 32 + nn] =
                    __ldg((const float4*)(xb + (size_t)(k0 + kr) * NN + nn));
            }
        }
        // stage W chunk transposed: Wt[kk][m] <- W[m][k0+kk]
        {
            #pragma unroll
            for (int p = 0; p < 8; p++) {
                const int task = t + p * 128;   // 1024 tasks
                const int m  = task >> 4;       // [0,64)
                const int kg = task & 15;       // [0,16)
                float4 wv = __ldg((const float4*)(W + (size_t)m * HID + k0 + kg * 4));
                Wt[(kg * 4 + 0) * WT_PITCH + m] = wv.x;
                Wt[(kg * 4 + 1) * WT_PITCH + m] = wv.y;
                Wt[(kg * 4 + 2) * WT_PITCH + m] = wv.z;
                Wt[(kg * 4 + 3) * WT_PITCH + m] = wv.w;
            }
        }
        __syncthreads();

        #pragma unroll 4
        for (int kk = 0; kk < KCHUNK; kk++) {
            const ulonglong2 wp2 = *(const ulonglong2*)&Wt[kk * WT_PITCH + m0];
            const float4 xv = *(const float4*)&xs[kk * 32 + nt0];
            const uint64_t x0 = pack2(xv.x, xv.x);
            const uint64_t x1 = pack2(xv.y, xv.y);
            const uint64_t x2 = pack2(xv.z, xv.z);
            const uint64_t x3 = pack2(xv.w, xv.w);
            acc[0][0] = fma2(wp2.x, x0, acc[0][0]);
            acc[0][1] = fma2(wp2.x, x1, acc[0][1]);
            acc[0][2] = fma2(wp2.x, x2, acc[0][2]);
            acc[0][3] = fma2(wp2.x, x3, acc[0][3]);
            acc[1][0] = fma2(wp2.y, x0, acc[1][0]);
            acc[1][1] = fma2(wp2.y, x1, acc[1][1]);
            acc[1][2] = fma2(wp2.y, x2, acc[1][2]);
            acc[1][3] = fma2(wp2.y, x3, acc[1][3]);
        }
    }

    // scatter into head-layout slot kh (plain stores; consumers sum slots).
    //   channel o, position n  ->  d = o>>4, a = o&15, b2 = n>>4, h = n&15, n2 = a*64+b2
    float* qdst = g_qh[kh];
    float* kdst = g_kd[kh];
    float* vdst = g_vd[kh];
    #pragma unroll
    for (int p = 0; p < 2; p++) {
        #pragma unroll
        for (int j = 0; j < 4; j++) {
            float vlo, vhi;
            unpack2(acc[p][j], vlo, vhi);
            const int np = n0g + nt0 + j;
            const int b2 = np >> 4, h = np & 15;
            const float vv[2] = {vlo, vhi};
            #pragma unroll
            for (int e = 0; e < 2; e++) {
                const int o = m0 + p * 2 + e;
                const int d = o >> 4, a = o & 15;
                const int n2 = a * 64 + b2;
                const float val = vv[e];
                if (z == 0)      qdst[(((b * HH + h) * NN + n2) << 2) + d] = val * QPRE;
                else if (z == 1) kdst[((b * HH + h) * DD + d) * NN + n2] = val;
                else             vdst[((b * HH + h) * DD + d) * NN + n2] = val;
            }
        }
    }
}

// ---------------- kernel 2: fused attention (f32x2 packed, depth-2 bias pipeline) ----------------
// grid (32, 64): x = 32-row chunk, y = bh. block 128 (4 warps).
// Stages K,V as sum of the two split-K slots; q likewise.
__global__ void __launch_bounds__(128) attn_kernel(const float* __restrict__ bias)
{
    __shared__ __align__(16) float sK[DD * NN];
    __shared__ __align__(16) float sV[DD * NN];

    const int bh    = blockIdx.y;
    const int chunk = blockIdx.x;
    const int t     = threadIdx.x;

    // load K,V head tiles (sum of split-K slots) into smem
    {
        const float4* gk0 = (const float4*)(g_kd[0] + bh * DD * NN);
        const float4* gk1 = (const float4*)(g_kd[1] + bh * DD * NN);
        const float4* gv0 = (const float4*)(g_vd[0] + bh * DD * NN);
        const float4* gv1 = (const float4*)(g_vd[1] + bh * DD * NN);
        float4* sk4 = (float4*)sK;
        float4* sv4 = (float4*)sV;
        #pragma unroll
        for (int i = 0; i < 8; i++) {
            const int idx = t + i * 128;
            float4 a = gk0[idx], bq = gk1[idx];
            sk4[idx] = make_float4(a.x + bq.x, a.y + bq.y, a.z + bq.z, a.w + bq.w);
            float4 c = gv0[idx], dq = gv1[idx];
            sv4[idx] = make_float4(c.x + dq.x, c.y + dq.y, c.z + dq.z, c.w + dq.w);
        }
    }
    __syncthreads();

    const int warp = t >> 5, lane = t & 31;
    const ulonglong2* sk2 = (const ulonglong2*)sK;   // [d*256 + mi] -> pairs (m0,m1),(m2,m3)
    const ulonglong2* sv2 = (const ulonglong2*)sV;
    const float*  biasbh = bias + (size_t)bh * NN * NN;
    const uint64_t L2E2 = pack2(LOG2E, LOG2E);

    #pragma unroll 1
    for (int pass = 0; pass < 2; pass++) {
        const int row0 = chunk * 32 + warp * 8 + pass * 4;

        uint64_t q2[4][4];                 // packed duplicated q components
        const ulonglong2* bp[4];
        #pragma unroll
        for (int j = 0; j < 4; j++) {
            const float4 qa = *(const float4*)(g_qh[0] + (bh * NN + row0 + j) * 4);
            const float4 qb = *(const float4*)(g_qh[1] + (bh * NN + row0 + j) * 4);
            const float qx = qa.x + qb.x, qy = qa.y + qb.y;
            const float qz = qa.z + qb.z, qw = qa.w + qb.w;
            q2[j][0] = pack2(qx, qx);
            q2[j][1] = pack2(qy, qy);
            q2[j][2] = pack2(qz, qz);
            q2[j][3] = pack2(qw, qw);
            bp[j] = (const ulonglong2*)(biasbh + (size_t)(row0 + j) * NN);
        }

        uint64_t sum2[4];
        uint64_t acc2[4][4];
        #pragma unroll
        for (int j = 0; j < 4; j++) {
            sum2[j] = 0ull;
            #pragma unroll
            for (int d = 0; d < 4; d++) acc2[j][d] = 0ull;
        }

        // prologue: bias for i=0 and i=1 (8 LDG.128 in flight)
        ulonglong2 buf[2][4];
        #pragma unroll
        for (int j = 0; j < 4; j++) buf[0][j] = __ldg(&bp[j][lane]);
        #pragma unroll
        for (int j = 0; j < 4; j++) buf[1][j] = __ldg(&bp[j][32 + lane]);

        #pragma unroll
        for (int i = 0; i < 8; i++) {
            const int mi = i * 32 + lane;           // float4 index into m
            // issue loads for i+2 before computing i (keeps 8 in flight)
            ulonglong2 bbn[4];
            if (i < 6) {
                const int min2 = mi + 64;
                #pragma unroll
                for (int j = 0; j < 4; j++) bbn[j] = __ldg(&bp[j][min2]);
            }

            const ulonglong2 k0 = sk2[mi];
            const ulonglong2 k1 = sk2[256 + mi];
            const ulonglong2 k2 = sk2[512 + mi];
            const ulonglong2 k3 = sk2[768 + mi];
            const ulonglong2 v0 = sv2[mi];
            const ulonglong2 v1 = sv2[256 + mi];
            const ulonglong2 v2 = sv2[512 + mi];
            const ulonglong2 v3 = sv2[768 + mi];

            #pragma unroll
            for (int j = 0; j < 4; j++) {
                const ulonglong2 bb = buf[i & 1][j];
                // scores for m-pair (0,1) and (2,3): z = q.k (q pre-scaled), then + bias*log2e
                uint64_t z01 = mul2(q2[j][0], k0.x);
                uint64_t z23 = mul2(q2[j][0], k0.y);
                z01 = fma2(q2[j][1], k1.x, z01);
                z23 = fma2(q2[j][1], k1.y, z23);
                z01 = fma2(q2[j][2], k2.x, z01);
                z23 = fma2(q2[j][2], k2.y, z23);
                z01 = fma2(q2[j][3], k3.x, z01);
                z23 = fma2(q2[j][3], k3.y, z23);
                z01 = fma2(bb.x, L2E2, z01);
                z23 = fma2(bb.y, L2E2, z23);
                float f0, f1, f2, f3;
                unpack2(z01, f0, f1);
                unpack2(z23, f2, f3);
                const uint64_t e01 = pack2(ex2f(f0), ex2f(f1));
                const uint64_t e23 = pack2(ex2f(f2), ex2f(f3));
                sum2[j] = add2(sum2[j], add2(e01, e23));
                acc2[j][0] = fma2(e01, v0.x, acc2[j][0]);
                acc2[j][0] = fma2(e23, v0.y, acc2[j][0]);
                acc2[j][1] = fma2(e01, v1.x, acc2[j][1]);
                acc2[j][1] = fma2(e23, v1.y, acc2[j][1]);
                acc2[j][2] = fma2(e01, v2.x, acc2[j][2]);
                acc2[j][2] = fma2(e23, v2.y, acc2[j][2]);
                acc2[j][3] = fma2(e01, v3.x, acc2[j][3]);
                acc2[j][3] = fma2(e23, v3.y, acc2[j][3]);
            }

            if (i < 6) {
                #pragma unroll
                for (int j = 0; j < 4; j++) buf[i & 1][j] = bbn[j];
            }
        }

        // collapse pairs, warp-reduce, lane 0 writes
        #pragma unroll
        for (int j = 0; j < 4; j++) {
            float slo, shi;
            unpack2(sum2[j], slo, shi);
            float sum = wred(slo + shi);
            float acc[4];
            #pragma unroll
            for (int d = 0; d < 4; d++) {
                float alo, ahi;
                unpack2(acc2[j][d], alo, ahi);
                acc[d] = wred(alo + ahi);
            }
            if (lane == 0) {
                float* ob = g_x2 + bh * 4 * NN;   // channel base = 4*bh
                const float inv = 1.0f / sum;
                #pragma unroll
                for (int d = 0; d < 4; d++)
                    ob[d * NN + row0 + j] = acc[d] * inv;
            }
        }
    }
}

// ---------------- kernel 3: smem-tiled f32x2 output GEMM + BN + LeakyReLU -------
// grid (64, 4, BB) = 1024 CTAs: x = 16-wide n-tile, y = 64-wide m-tile, z = batch.
// block 128: mg = t&15 -> 4 m (2 packed pairs), ng = t>>4 -> 2 n.
__global__ void __launch_bounds__(128) out_kernel(
    const float* __restrict__ Wo, const float* __restrict__ bo,
    const float* __restrict__ gamma, const float* __restrict__ beta,
    const float* __restrict__ rmean, const float* __restrict__ rvar,
    float* __restrict__ out)
{
    __shared__ __align__(16) float xs[KCHUNK * 16];
    __shared__ __align__(16) float Wt[KCHUNK * WT_PITCH];

    const int n0g = blockIdx.x * 16;
    const int m0g = blockIdx.y * 64;
    const int b   = blockIdx.z;

    const int t   = threadIdx.x;
    const int mg  = t & 15;
    const int ng  = t >> 4;            // [0,8)
    const int m0  = mg * 4;
    const int nt0 = ng * 2;

    // stage x chunk [64c x 16n] from g_x2, coalesced (256 float4 tasks)
    {
        const int nn = (t & 3) * 4;
        const int kk = t >> 2;          // [0,32)
        const float* xb = g_x2 + (size_t)b * 64 * NN + n0g;
        #pragma unroll
        for (int p = 0; p < 2; p++) {
            const int kr = kk + p * 32;
            *(float4*)&xs[kr * 16 + nn] = *(const float4*)(xb + (size_t)kr * NN + nn);
        }
    }
    // stage Wo tile transposed: Wt[kk][m] <- Wo[m0g+m][kk]
    {
        #pragma unroll
        for (int p = 0; p < 8; p++) {
            const int task = t + p * 128;   // 1024 tasks
            const int m  = task >> 4;       // [0,64)
            const int kg = task & 15;       // [0,16)
            float4 wv = __ldg((const float4*)(Wo + (size_t)(m0g + m) * 64 + kg * 4));
            Wt[(kg * 4 + 0) * WT_PITCH + m] = wv.x;
            Wt[(kg * 4 + 1) * WT_PITCH + m] = wv.y;
            Wt[(kg * 4 + 2) * WT_PITCH + m] = wv.z;
            Wt[(kg * 4 + 3) * WT_PITCH + m] = wv.w;
        }
    }
    __syncthreads();

    uint64_t acc[2][2];
    #pragma unroll
    for (int p = 0; p < 2; p++)
        #pragma unroll
        for (int j = 0; j < 2; j++) acc[p][j] = 0ull;

    #pragma unroll 4
    for (int kk = 0; kk < KCHUNK; kk++) {
        const ulonglong2 wp2 = *(const ulonglong2*)&Wt[kk * WT_PITCH + m0];
        const float2 xv = *(const float2*)&xs[kk * 16 + nt0];
        const uint64_t x0 = pack2(xv.x, xv.x);
        const uint64_t x1 = pack2(xv.y, xv.y);
        acc[0][0] = fma2(wp2.x, x0, acc[0][0]);
        acc[0][1] = fma2(wp2.x, x1, acc[0][1]);
        acc[1][0] = fma2(wp2.y, x0, acc[1][0]);
        acc[1][1] = fma2(wp2.y, x1, acc[1][1]);
    }

    // BN(eval) + LeakyReLU epilogue
    #pragma unroll
    for (int p = 0; p < 2; p++) {
        const int o0 = m0g + m0 + p * 2;
        float sc[2], bse[2];
        #pragma unroll
        for (int e = 0; e < 2; e++) {
            const int o = o0 + e;
            const float inv = rsqrtf(__ldg(rvar + o) + 1e-5f);
            sc[e]  = __ldg(gamma + o) * inv;
            bse[e] = fmaf(__ldg(bo + o), sc[e], __ldg(beta + o) - __ldg(rmean + o) * sc[e]);
        }
        #pragma unroll
        for (int j = 0; j < 2; j++) {
            float vlo, vhi;
            unpack2(acc[p][j], vlo, vhi);
            const int n = n0g + nt0 + j;
            float r0 = fmaf(vlo, sc[0], bse[0]);
            float r1 = fmaf(vhi, sc[1], bse[1]);
            r0 = r0 > 0.f ? r0 : 0.2f * r0;
            r1 = r1 > 0.f ? r1 : 0.2f * r1;
            out[((size_t)b * HID + o0) * NN + n]     = r0;
            out[((size_t)b * HID + o0 + 1) * NN + n] = r1;
        }
    }
}

// ---------------- launch ----------------
extern "C" void kernel_launch(void* const* d_in, const int* in_sizes, int n_in,
                              void* d_out, int out_size)
{
    const float* q    = (const float*)d_in[0];
    const float* k    = (const float*)d_in[1];
    const float* v    = (const float*)d_in[2];
    const float* bias = (const float*)d_in[3];
    const float* Wq   = (const float*)d_in[4];
    const float* Wk   = (const float*)d_in[5];
    const float* Wv   = (const float*)d_in[6];
    const float* Wo   = (const float*)d_in[7];
    const float* bo   = (const float*)d_in[8];
    const float* gm   = (const float*)d_in[9];
    const float* bt   = (const float*)d_in[10];
    const float* rm   = (const float*)d_in[11];
    const float* rv   = (const float*)d_in[12];
    float* out = (float*)d_out;

    proj_kernel<<<dim3(64, BB, 3), 128>>>(q, k, v, Wq, Wk, Wv);
    attn_kernel<<<dim3(32, BB * HH), 128>>>(bias);
    out_kernel<<<dim3(64, 4, BB), 128>>>(Wo, bo, gm, bt, rm, rv, out);
}

// round 16
// speedup vs baseline: 1.1429x; 1.1429x over previous
#include <cuda_runtime.h>
#include <cstdint>

#define BB 4
#define HH 16
#define DD 4
#define HID 256
#define NN 1024
#define LOG2E 1.4426950408889634f
#define QPRE (0.5f * LOG2E)   /* SCALE * log2(e), folded into q at projection time */

// ---------------- device scratch (no allocation allowed) ----------------
__device__ float g_qh[BB*HH*NN*DD];   // [b][h][n][d], pre-scaled by QPRE
__device__ float g_kd[BB*HH*DD*NN];   // [b][h][d][n]
__device__ float g_vd[BB*HH*DD*NN];   // [b][h][d][n]
__device__ float g_x2[BB*HH*DD*NN];   // [b][h*4+d][n]  (post-transpose layout)

__device__ __forceinline__ float ex2f(float x){
    float y; asm("ex2.approx.ftz.f32 %0, %1;" : "=f"(y) : "f"(x)); return y;
}
__device__ __forceinline__ float wred(float v){
    v += __shfl_xor_sync(0xffffffffu, v, 16);
    v += __shfl_xor_sync(0xffffffffu, v, 8);
    v += __shfl_xor_sync(0xffffffffu, v, 4);
    v += __shfl_xor_sync(0xffffffffu, v, 2);
    v += __shfl_xor_sync(0xffffffffu, v, 1);
    return v;
}

// ---- packed f32x2 helpers (PTX ISA 8.6+, sm_100+) ----
__device__ __forceinline__ uint64_t fma2(uint64_t a, uint64_t b, uint64_t c){
    uint64_t d; asm("fma.rn.f32x2 %0, %1, %2, %3;" : "=l"(d) : "l"(a), "l"(b), "l"(c)); return d;
}
__device__ __forceinline__ uint64_t mul2(uint64_t a, uint64_t b){
    uint64_t d; asm("mul.rn.f32x2 %0, %1, %2;" : "=l"(d) : "l"(a), "l"(b)); return d;
}
__device__ __forceinline__ uint64_t add2(uint64_t a, uint64_t b){
    uint64_t d; asm("add.rn.f32x2 %0, %1, %2;" : "=l"(d) : "l"(a), "l"(b)); return d;
}
__device__ __forceinline__ uint64_t pack2(float lo, float hi){
    uint64_t d; asm("mov.b64 %0, {%1, %2};" : "=l"(d) : "f"(lo), "f"(hi)); return d;
}
__device__ __forceinline__ void unpack2(uint64_t p, float& lo, float& hi){
    asm("mov.b64 {%0, %1}, %2;" : "=f"(lo), "=f"(hi) : "l"(p));
}

#define WT_PITCH 68   /* floats; 272B rows, 16B-aligned */
#define KCHUNK 64

// ---------------- kernel 0: zero the projection scratch (for split-K atomics) ----
__global__ void zero_kernel()
{
    const int i = blockIdx.x * blockDim.x + threadIdx.x;   // [0, 65536)
    const float4 z = make_float4(0.f, 0.f, 0.f, 0.f);
    ((float4*)g_qh)[i] = z;
    ((float4*)g_kd)[i] = z;
    ((float4*)g_vd)[i] = z;
}

// ---------------- kernel 1: smem-tiled f32x2 GEMM, split-K, + head scatter ------
// grid (64, BB, 3): x = (n-tile [0,32) | k-half<<5), y = batch, z = projection.
// block 128: mg = t&15 -> 4 consecutive M (2 packed pairs), ng = t>>4 -> 4 N.
// Each CTA covers K range [kh*128, kh*128+128); partials via atomicAdd.
__global__ void __launch_bounds__(128) proj_kernel(
    const float* __restrict__ q,
    const float* __restrict__ k,
    const float* __restrict__ v,
    const float* __restrict__ Wq,
    const float* __restrict__ Wk,
    const float* __restrict__ Wv)
{
    __shared__ __align__(16) float xs[KCHUNK * 32];
    __shared__ __align__(16) float Wt[KCHUNK * WT_PITCH];

    const int z   = blockIdx.z;
    const int b   = blockIdx.y;
    const int nt  = blockIdx.x & 31;
    const int kh  = blockIdx.x >> 5;           // k-half: 0 or 1
    const int n0g = nt * 32;

    const float* x = (z == 0) ? q : (z == 1) ? k : v;
    const float* W = (z == 0) ? Wq : (z == 1) ? Wk : Wv;

    const int t   = threadIdx.x;
    const int mg  = t & 15;
    const int ng  = t >> 4;            // [0,8)
    const int m0  = mg * 4;
    const int nt0 = ng * 4;

    uint64_t acc[2][4];
    #pragma unroll
    for (int p = 0; p < 2; p++)
        #pragma unroll
        for (int j = 0; j < 4; j++) acc[p][j] = 0ull;

    const float* xb = x + (size_t)b * HID * NN + n0g;

    const int kbeg = kh * 128;
    for (int k0 = kbeg; k0 < kbeg + 128; k0 += KCHUNK) {
        __syncthreads();
        // stage x chunk [64k x 32n], coalesced
        {
            const int kk = t >> 3;          // [0,16)
            const int nn = (t & 7) * 4;
            #pragma unroll
            for (int p = 0; p < 4; p++) {
                const int kr = kk + p * 16;
                *(float4*)&xs[kr * 32 + nn] =
                    __ldg((const float4*)(xb + (size_t)(k0 + kr) * NN + nn));
            }
        }
        // stage W chunk transposed: Wt[kk][m] <- W[m][k0+kk]
        {
            #pragma unroll
            for (int p = 0; p < 8; p++) {
                const int task = t + p * 128;   // 1024 tasks
                const int m  = task >> 4;       // [0,64)
                const int kg = task & 15;       // [0,16)
                float4 wv = __ldg((const float4*)(W + (size_t)m * HID + k0 + kg * 4));
                Wt[(kg * 4 + 0) * WT_PITCH + m] = wv.x;
                Wt[(kg * 4 + 1) * WT_PITCH + m] = wv.y;
                Wt[(kg * 4 + 2) * WT_PITCH + m] = wv.z;
                Wt[(kg * 4 + 3) * WT_PITCH + m] = wv.w;
            }
        }
        __syncthreads();

        #pragma unroll 4
        for (int kk = 0; kk < KCHUNK; kk++) {
            const ulonglong2 wp2 = *(const ulonglong2*)&Wt[kk * WT_PITCH + m0];
            const float4 xv = *(const float4*)&xs[kk * 32 + nt0];
            const uint64_t x0 = pack2(xv.x, xv.x);
            const uint64_t x1 = pack2(xv.y, xv.y);
            const uint64_t x2 = pack2(xv.z, xv.z);
            const uint64_t x3 = pack2(xv.w, xv.w);
            acc[0][0] = fma2(wp2.x, x0, acc[0][0]);
            acc[0][1] = fma2(wp2.x, x1, acc[0][1]);
            acc[0][2] = fma2(wp2.x, x2, acc[0][2]);
            acc[0][3] = fma2(wp2.x, x3, acc[0][3]);
            acc[1][0] = fma2(wp2.y, x0, acc[1][0]);
            acc[1][1] = fma2(wp2.y, x1, acc[1][1]);
            acc[1][2] = fma2(wp2.y, x2, acc[1][2]);
            acc[1][3] = fma2(wp2.y, x3, acc[1][3]);
        }
    }

    // scatter-accumulate into head layouts (split-K partials).
    //   channel o, position n  ->  d = o>>4, a = o&15, b2 = n>>4, h = n&15, n2 = a*64+b2
    #pragma unroll
    for (int p = 0; p < 2; p++) {
        #pragma unroll
        for (int j = 0; j < 4; j++) {
            float vlo, vhi;
            unpack2(acc[p][j], vlo, vhi);
            const int np = n0g + nt0 + j;
            const int b2 = np >> 4, h = np & 15;
            const float vv[2] = {vlo, vhi};
            #pragma unroll
            for (int e = 0; e < 2; e++) {
                const int o = m0 + p * 2 + e;
                const int d = o >> 4, a = o & 15;
                const int n2 = a * 64 + b2;
                const float val = vv[e];
                if (z == 0)      atomicAdd(&g_qh[(((b * HH + h) * NN + n2) << 2) + d], val * QPRE);
                else if (z == 1) atomicAdd(&g_kd[((b * HH + h) * DD + d) * NN + n2], val);
                else             atomicAdd(&g_vd[((b * HH + h) * DD + d) * NN + n2], val);
            }
        }
    }
}

// ---------------- kernel 2: fused attention (f32x2, 8 warps, single pass) -------
// grid (32, 64): x = 32-row chunk, y = bh. block 256 (8 warps).
// Each warp: 4 rows, ONE pass (half the serial chain of the 128-thread version;
// no mid-kernel pipeline restart). Depth-2 bias pipeline (8 LDG.128 in flight).
__global__ void __launch_bounds__(256) attn_kernel(const float* __restrict__ bias)
{
    __shared__ __align__(16) float sK[DD * NN];
    __shared__ __align__(16) float sV[DD * NN];

    const int bh    = blockIdx.y;
    const int chunk = blockIdx.x;
    const int t     = threadIdx.x;

    // load K,V head tiles (4096 floats each = 1024 float4) into smem
    {
        const float4* gk = (const float4*)(g_kd + bh * DD * NN);
        const float4* gv = (const float4*)(g_vd + bh * DD * NN);
        float4* sk4 = (float4*)sK;
        float4* sv4 = (float4*)sV;
        #pragma unroll
        for (int i = 0; i < 4; i++) {
            sk4[t + i * 256] = gk[t + i * 256];
            sv4[t + i * 256] = gv[t + i * 256];
        }
    }
    __syncthreads();

    const int warp = t >> 5, lane = t & 31;
    const ulonglong2* sk2 = (const ulonglong2*)sK;   // [d*256 + mi] -> pairs (m0,m1),(m2,m3)
    const ulonglong2* sv2 = (const ulonglong2*)sV;
    const float*  biasbh = bias + (size_t)bh * NN * NN;
    const uint64_t L2E2 = pack2(LOG2E, LOG2E);

    const int row0 = chunk * 32 + warp * 4;

    uint64_t q2[4][4];                 // packed duplicated q components
    const ulonglong2* bp[4];
    #pragma unroll
    for (int j = 0; j < 4; j++) {
        float4 qr = *(const float4*)(g_qh + (bh * NN + row0 + j) * 4);
        q2[j][0] = pack2(qr.x, qr.x);
        q2[j][1] = pack2(qr.y, qr.y);
        q2[j][2] = pack2(qr.z, qr.z);
        q2[j][3] = pack2(qr.w, qr.w);
        bp[j] = (const ulonglong2*)(biasbh + (size_t)(row0 + j) * NN);
    }

    uint64_t sum2[4];
    uint64_t acc2[4][4];
    #pragma unroll
    for (int j = 0; j < 4; j++) {
        sum2[j] = 0ull;
        #pragma unroll
        for (int d = 0; d < 4; d++) acc2[j][d] = 0ull;
    }

    // prologue: bias for i=0 and i=1 (8 LDG.128 in flight)
    ulonglong2 buf[2][4];
    #pragma unroll
    for (int j = 0; j < 4; j++) buf[0][j] = __ldg(&bp[j][lane]);
    #pragma unroll
    for (int j = 0; j < 4; j++) buf[1][j] = __ldg(&bp[j][32 + lane]);

    #pragma unroll
    for (int i = 0; i < 8; i++) {
        const int mi = i * 32 + lane;           // float4 index into m
        // issue loads for i+2 before computing i (keeps 8 in flight)
        ulonglong2 bbn[4];
        if (i < 6) {
            const int min2 = mi + 64;
            #pragma unroll
            for (int j = 0; j < 4; j++) bbn[j] = __ldg(&bp[j][min2]);
        }

        const ulonglong2 k0 = sk2[mi];
        const ulonglong2 k1 = sk2[256 + mi];
        const ulonglong2 k2 = sk2[512 + mi];
        const ulonglong2 k3 = sk2[768 + mi];
        const ulonglong2 v0 = sv2[mi];
        const ulonglong2 v1 = sv2[256 + mi];
        const ulonglong2 v2 = sv2[512 + mi];
        const ulonglong2 v3 = sv2[768 + mi];

        #pragma unroll
        for (int j = 0; j < 4; j++) {
            const ulonglong2 bb = buf[i & 1][j];
            // scores for m-pair (0,1) and (2,3): z = q.k (q pre-scaled), then + bias*log2e
            uint64_t z01 = mul2(q2[j][0], k0.x);
            uint64_t z23 = mul2(q2[j][0], k0.y);
            z01 = fma2(q2[j][1], k1.x, z01);
            z23 = fma2(q2[j][1], k1.y, z23);
            z01 = fma2(q2[j][2], k2.x, z01);
            z23 = fma2(q2[j][2], k2.y, z23);
            z01 = fma2(q2[j][3], k3.x, z01);
            z23 = fma2(q2[j][3], k3.y, z23);
            z01 = fma2(bb.x, L2E2, z01);
            z23 = fma2(bb.y, L2E2, z23);
            float f0, f1, f2, f3;
            unpack2(z01, f0, f1);
            unpack2(z23, f2, f3);
            const uint64_t e01 = pack2(ex2f(f0), ex2f(f1));
            const uint64_t e23 = pack2(ex2f(f2), ex2f(f3));
            sum2[j] = add2(sum2[j], add2(e01, e23));
            acc2[j][0] = fma2(e01, v0.x, acc2[j][0]);
            acc2[j][0] = fma2(e23, v0.y, acc2[j][0]);
            acc2[j][1] = fma2(e01, v1.x, acc2[j][1]);
            acc2[j][1] = fma2(e23, v1.y, acc2[j][1]);
            acc2[j][2] = fma2(e01, v2.x, acc2[j][2]);
            acc2[j][2] = fma2(e23, v2.y, acc2[j][2]);
            acc2[j][3] = fma2(e01, v3.x, acc2[j][3]);
            acc2[j][3] = fma2(e23, v3.y, acc2[j][3]);
        }

        if (i < 6) {
            #pragma unroll
            for (int j = 0; j < 4; j++) buf[i & 1][j] = bbn[j];
        }
    }

    // collapse pairs, warp-reduce, lane 0 writes
    #pragma unroll
    for (int j = 0; j < 4; j++) {
        float slo, shi;
        unpack2(sum2[j], slo, shi);
        float sum = wred(slo + shi);
        float acc[4];
        #pragma unroll
        for (int d = 0; d < 4; d++) {
            float alo, ahi;
            unpack2(acc2[j][d], alo, ahi);
            acc[d] = wred(alo + ahi);
        }
        if (lane == 0) {
            float* ob = g_x2 + bh * 4 * NN;   // channel base = 4*bh
            const float inv = 1.0f / sum;
            #pragma unroll
            for (int d = 0; d < 4; d++)
                ob[d * NN + row0 + j] = acc[d] * inv;
        }
    }
}

// ---------------- kernel 3: smem-tiled f32x2 output GEMM + BN + LeakyReLU -------
// grid (32, 4, BB): x = n-tile, y = 64-wide m-tile, z = batch. block 128.
__global__ void __launch_bounds__(128) out_kernel(
    const float* __restrict__ Wo, const float* __restrict__ bo,
    const float* __restrict__ gamma, const float* __restrict__ beta,
    const float* __restrict__ rmean, const float* __restrict__ rvar,
    float* __restrict__ out)
{
    __shared__ __align__(16) float xs[KCHUNK * 32];
    __shared__ __align__(16) float Wt[KCHUNK * WT_PITCH];

    const int n0g = blockIdx.x * 32;
    const int m0g = blockIdx.y * 64;
    const int b   = blockIdx.z;

    const int t   = threadIdx.x;
    const int mg  = t & 15;
    const int ng  = t >> 4;            // [0,8)
    const int m0  = mg * 4;
    const int nt0 = ng * 4;

    // stage x chunk [64c x 32n] from g_x2, coalesced
    {
        const int kk = t >> 3;          // [0,16)
        const int nn = (t & 7) * 4;
        const float* xb = g_x2 + (size_t)b * 64 * NN + n0g;
        #pragma unroll
        for (int p = 0; p < 4; p++) {
            const int kr = kk + p * 16;
            *(float4*)&xs[kr * 32 + nn] = *(const float4*)(xb + (size_t)kr * NN + nn);
        }
    }
    // stage Wo tile transposed: Wt[kk][m] <- Wo[m0g+m][kk]
    {
        #pragma unroll
        for (int p = 0; p < 8; p++) {
            const int task = t + p * 128;   // 1024 tasks
            const int m  = task >> 4;       // [0,64)
            const int kg = task & 15;       // [0,16)
            float4 wv = __ldg((const float4*)(Wo + (size_t)(m0g + m) * 64 + kg * 4));
            Wt[(kg * 4 + 0) * WT_PITCH + m] = wv.x;
            Wt[(kg * 4 + 1) * WT_PITCH + m] = wv.y;
            Wt[(kg * 4 + 2) * WT_PITCH + m] = wv.z;
            Wt[(kg * 4 + 3) * WT_PITCH + m] = wv.w;
        }
    }
    __syncthreads();

    uint64_t acc[2][4];
    #pragma unroll
    for (int p = 0; p < 2; p++)
        #pragma unroll
        for (int j = 0; j < 4; j++) acc[p][j] = 0ull;

    #pragma unroll 4
    for (int kk = 0; kk < KCHUNK; kk++) {
        const ulonglong2 wp2 = *(const ulonglong2*)&Wt[kk * WT_PITCH + m0];
        const float4 xv = *(const float4*)&xs[kk * 32 + nt0];
        const uint64_t x0 = pack2(xv.x, xv.x);
        const uint64_t x1 = pack2(xv.y, xv.y);
        const uint64_t x2 = pack2(xv.z, xv.z);
        const uint64_t x3 = pack2(xv.w, xv.w);
        acc[0][0] = fma2(wp2.x, x0, acc[0][0]);
        acc[0][1] = fma2(wp2.x, x1, acc[0][1]);
        acc[0][2] = fma2(wp2.x, x2, acc[0][2]);
        acc[0][3] = fma2(wp2.x, x3, acc[0][3]);
        acc[1][0] = fma2(wp2.y, x0, acc[1][0]);
        acc[1][1] = fma2(wp2.y, x1, acc[1][1]);
        acc[1][2] = fma2(wp2.y, x2, acc[1][2]);
        acc[1][3] = fma2(wp2.y, x3, acc[1][3]);
    }

    // BN(eval) + LeakyReLU epilogue; scalar stores (4 o x 4 n per thread)
    #pragma unroll
    for (int p = 0; p < 2; p++) {
        const int o0 = m0g + m0 + p * 2;
        float sc[2], bse[2];
        #pragma unroll
        for (int e = 0; e < 2; e++) {
            const int o = o0 + e;
            const float inv = rsqrtf(__ldg(rvar + o) + 1e-5f);
            sc[e]  = __ldg(gamma + o) * inv;
            bse[e] = fmaf(__ldg(bo + o), sc[e], __ldg(beta + o) - __ldg(rmean + o) * sc[e]);
        }
        #pragma unroll
        for (int j = 0; j < 4; j++) {
            float vlo, vhi;
            unpack2(acc[p][j], vlo, vhi);
            const int n = n0g + nt0 + j;
            float r0 = fmaf(vlo, sc[0], bse[0]);
            float r1 = fmaf(vhi, sc[1], bse[1]);
            r0 = r0 > 0.f ? r0 : 0.2f * r0;
            r1 = r1 > 0.f ? r1 : 0.2f * r1;
            out[((size_t)b * HID + o0) * NN + n]     = r0;
            out[((size_t)b * HID + o0 + 1) * NN + n] = r1;
        }
    }
}

// ---------------- launch ----------------
extern "C" void kernel_launch(void* const* d_in, const int* in_sizes, int n_in,
                              void* d_out, int out_size)
{
    const float* q    = (const float*)d_in[0];
    const float* k    = (const float*)d_in[1];
    const float* v    = (const float*)d_in[2];
    const float* bias = (const float*)d_in[3];
    const float* Wq   = (const float*)d_in[4];
    const float* Wk   = (const float*)d_in[5];
    const float* Wv   = (const float*)d_in[6];
    const float* Wo   = (const float*)d_in[7];
    const float* bo   = (const float*)d_in[8];
    const float* gm   = (const float*)d_in[9];
    const float* bt   = (const float*)d_in[10];
    const float* rm   = (const float*)d_in[11];
    const float* rv   = (const float*)d_in[12];
    float* out = (float*)d_out;

    zero_kernel<<<256, 256>>>();
    proj_kernel<<<dim3(64, BB, 3), 128>>>(q, k, v, Wq, Wk, Wv);
    attn_kernel<<<dim3(32, BB * HH), 256>>>(bias);
    out_kernel<<<dim3(32, 4, BB), 128>>>(Wo, bo, gm, bt, rm, rv, out);
}